// round 3
// baseline (speedup 1.0000x reference)
#include <cuda_runtime.h>
#include <cstdint>

// ----------------------------------------------------------------------------
// ProposalLayer (RPN): decode anchors -> top-6000 (stable) -> greedy NMS -> 300
// H=128, W=192, A=9, STRIDE=16, PRE_NMS=6000, POST_NMS=300, THRESH=0.7
// ----------------------------------------------------------------------------

#define HH 128
#define WW 192
#define HWSZ (HH * WW)          // 24576
#define NA 9
#define NTOT (NA * HWSZ)        // 221184
#define PRE_NMS 6000
#define POST_NMS 300
#define SEL_CAP 8192
#define COLB 94                 // ceil(6000/64)

typedef unsigned long long u64;
typedef unsigned int u32;

// Anchor widths/heights (x2-x1+1); all anchor centers are at (8,8) + 16*(w,h).
__constant__ float c_aw[NA] = {184.f, 368.f, 736.f, 128.f, 256.f, 512.f, 88.f, 176.f, 352.f};
__constant__ float c_ah[NA] = {96.f, 192.f, 384.f, 128.f, 256.f, 512.f, 176.f, 352.f, 704.f};

// ------------------------------- device state -------------------------------
__device__ float4 g_boxes[NTOT];                 // decoded boxes
__device__ u32 g_scf[NTOT];                      // order-preserving score keys
__device__ u64 g_sel[SEL_CAP];                   // selected keys (unsorted)
__device__ int g_selcnt;
__device__ u32 g_hist16[65536];
__device__ u32 g_hist8[256];
struct SelState { u32 prefix; int krem; int done; u32 thresh; };
__device__ SelState g_state;
__device__ float4 g_tboxes[PRE_NMS];             // top-6000 boxes, sorted order
__device__ u64 g_vbits[COLB];                    // validity bitmask of top-6000
__device__ u64 g_mask[(size_t)PRE_NMS * COLB];   // suppression bits (j > i only)

// ------------------------------- kernels ------------------------------------

__global__ void reset_kernel() {
    int i = blockIdx.x * 1024 + threadIdx.x;     // 65536 threads
    g_hist16[i] = 0u;
    if (i < 256) g_hist8[i] = 0u;
    if (i < COLB) g_vbits[i] = 0ull;
    if (i == 0) {
        g_state.prefix = 0u; g_state.krem = PRE_NMS;
        g_state.done = 0; g_state.thresh = 0u;
        g_selcnt = 0;
    }
}

// Decode boxes + build score keys + 16-bit-bucket global histogram (pass 0).
__global__ void decode_kernel(const float* __restrict__ scores,
                              const float* __restrict__ deltas,
                              const float* __restrict__ iminfo) {
    int t = blockIdx.x * blockDim.x + threadIdx.x;
    if (t >= NTOT) return;
    int a = t / HWSZ;
    int pix = t - a * HWSZ;
    int wi = pix % WW;
    int hi = pix / WW;

    float sc = scores[(NA + a) * HWSZ + pix];
    float dx = deltas[(4 * a + 0) * HWSZ + pix];
    float dy = deltas[(4 * a + 1) * HWSZ + pix];
    float dw = deltas[(4 * a + 2) * HWSZ + pix];
    float dh = deltas[(4 * a + 3) * HWSZ + pix];
    dw = fminf(fmaxf(dw, -10.f), 10.f);
    dh = fminf(fmaxf(dh, -10.f), 10.f);

    float AW = c_aw[a], AH = c_ah[a];
    float cx = dx * AW + (8.f + 16.f * (float)wi);
    float cy = dy * AH + (8.f + 16.f * (float)hi);
    float pw = __expf(dw) * AW;
    float ph = __expf(dh) * AH;
    float x1 = cx - 0.5f * pw, x2 = cx + 0.5f * pw;
    float y1 = cy - 0.5f * ph, y2 = cy + 0.5f * ph;

    float maxx = iminfo[1] - 1.0f;
    float maxy = iminfo[0] - 1.0f;
    x1 = fminf(fmaxf(x1, 0.f), maxx);
    x2 = fminf(fmaxf(x2, 0.f), maxx);
    y1 = fminf(fmaxf(y1, 0.f), maxy);
    y2 = fminf(fmaxf(y2, 0.f), maxy);

    float minsz = 16.f * iminfo[2];
    bool valid = (x2 - x1 + 1.0f >= minsz) && (y2 - y1 + 1.0f >= minsz);

    int i = pix * NA + a;  // reference flat ordering: ((h*W+w)*A + a)
    g_boxes[i] = make_float4(x1, y1, x2, y2);

    u32 u;
    if (valid) {
        u = __float_as_uint(sc);
        u = (u & 0x80000000u) ? ~u : (u | 0x80000000u);
    } else {
        u = 0x007FFFFFu;  // flip(-inf)
    }
    g_scf[i] = u;
    atomicAdd(&g_hist16[u >> 16], 1u);
}

// Pick 16-bit threshold bucket from 65536-bin histogram. One block, 1024 thr.
__global__ void pick16_kernel() {
    __shared__ u32 ssum[1024];
    int t = threadIdx.x;
    int hi = 65535 - (t << 6);  // descending chunk of 64 bins
    u32 s = 0;
    #pragma unroll 8
    for (int k = 0; k < 64; k++) s += g_hist16[hi - k];
    ssum[t] = s;
    __syncthreads();
    for (int off = 1; off < 1024; off <<= 1) {
        u32 add = (t >= off) ? ssum[t - off] : 0u;
        __syncthreads();
        ssum[t] += add;
        __syncthreads();
    }
    u32 incl = ssum[t];
    u32 before = (t > 0) ? ssum[t - 1] : 0u;
    if (before < (u32)PRE_NMS && incl >= (u32)PRE_NMS) {
        u32 c = before, hb = 0;
        int bstar = hi;
        for (int k = 0; k < 64; k++) {
            hb = g_hist16[hi - k];
            if (c + hb >= (u32)PRE_NMS) { bstar = hi - k; break; }
            c += hb;
        }
        u32 cge = c + hb;
        if (cge <= (u32)SEL_CAP) {
            g_state.done = 1;
            g_state.thresh = ((u32)bstar) << 16;
        } else {
            g_state.prefix = (u32)bstar;
            g_state.krem = PRE_NMS - (int)c;
            g_state.done = 0;
        }
    }
}

// Refinement pass (no-op unless the 16-bit bucket overflowed SEL_CAP).
__global__ void hist8_kernel() {
    if (g_state.done) return;
    __shared__ u32 sh[256];
    int tid = threadIdx.x;
    sh[tid] = 0u;
    __syncthreads();
    int i = blockIdx.x * blockDim.x + tid;
    u32 prefix = g_state.prefix;
    if (i < NTOT) {
        u32 v = g_scf[i];
        if ((v >> 16) == prefix) atomicAdd(&sh[(v >> 8) & 0xFFu], 1u);
    }
    __syncthreads();
    if (sh[tid]) atomicAdd(&g_hist8[tid], sh[tid]);
}

__global__ void pick8_kernel() {
    if (g_state.done) return;
    if (threadIdx.x != 0) return;
    int krem = g_state.krem;
    u32 c = 0;
    int b8 = 0;
    for (int bb = 255; bb >= 0; bb--) {
        u32 hh = g_hist8[bb];
        if (c + hh >= (u32)krem) { b8 = bb; break; }
        c += hh;
    }
    g_state.thresh = (g_state.prefix << 16) | ((u32)b8 << 8);
    g_state.done = 1;
}

__global__ void compact_kernel() {
    int i = blockIdx.x * blockDim.x + threadIdx.x;
    if (i >= NTOT) return;
    u32 v = g_scf[i];
    if (v >= g_state.thresh) {
        int p = atomicAdd(&g_selcnt, 1);
        if (p < SEL_CAP)
            g_sel[p] = ((u64)v << 32) | (u32)(~(u32)i);
    }
}

// One-block bitonic sort of 8192 u64 keys (descending) + fused gather of
// top-6000 boxes and validity bitmask. 64KB dynamic smem.
__global__ void sort_kernel() {
    extern __shared__ u64 s[];
    int tid = threadIdx.x;
    int cnt = g_selcnt;
    if (cnt > SEL_CAP) cnt = SEL_CAP;
    for (int i = tid; i < SEL_CAP; i += 1024)
        s[i] = (i < cnt) ? g_sel[i] : 0ull;
    __syncthreads();
    for (int k = 2; k <= SEL_CAP; k <<= 1) {
        for (int j = k >> 1; j > 0; j >>= 1) {
            for (int t = tid; t < SEL_CAP; t += 1024) {
                int ixj = t ^ j;
                if (ixj > t) {
                    u64 a = s[t], b = s[ixj];
                    bool sw = ((t & k) == 0) ? (a < b) : (a > b);
                    if (sw) { s[t] = b; s[ixj] = a; }
                }
            }
            __syncthreads();
        }
    }
    // gather top-6000 boxes in sorted order + validity bits
    for (int i = tid; i < PRE_NMS; i += 1024) {
        u64 key = s[i];
        u32 idx = ~(u32)key;
        g_tboxes[i] = g_boxes[idx];
        if ((u32)(key >> 32) >= 0x80000000u)
            atomicOr(&g_vbits[i >> 6], 1ull << (i & 63));
    }
}

// Suppression mask: row i, bit b of word cb says box j=cb*64+b (j>i) has
// IoU(i,j) > 0.7. Upper-triangular blocks only; lower stays zero (never written).
__global__ void nms_mask_kernel() {
    int rb = blockIdx.x, cb = blockIdx.y;
    if (cb < rb) return;
    __shared__ float4 cbox[64];
    __shared__ float carea[64];
    int t = threadIdx.x;
    int j0 = cb * 64;
    float4 bj0 = (j0 + t < PRE_NMS) ? g_tboxes[j0 + t] : make_float4(0.f, 0.f, 0.f, 0.f);
    cbox[t] = bj0;
    carea[t] = (bj0.z - bj0.x) * (bj0.w - bj0.y);
    __syncthreads();
    int i = rb * 64 + t;
    if (i >= PRE_NMS) return;
    float4 bi = g_tboxes[i];
    float ai = (bi.z - bi.x) * (bi.w - bi.y);
    u64 bits = 0ull;
    int jmax = min(64, PRE_NMS - j0);
    #pragma unroll 4
    for (int b = 0; b < jmax; b++) {
        int j = j0 + b;
        if (j <= i) continue;
        float4 bj = cbox[b];
        float xx1 = fmaxf(bi.x, bj.x), yy1 = fmaxf(bi.y, bj.y);
        float xx2 = fminf(bi.z, bj.z), yy2 = fminf(bi.w, bj.w);
        float w = fmaxf(xx2 - xx1, 0.f);
        float h = fmaxf(yy2 - yy1, 0.f);
        float inter = w * h;
        float iou = inter / (ai + carea[b] - inter);
        if (iou > 0.7f) bits |= (1ull << b);
    }
    g_mask[(size_t)i * COLB + cb] = bits;
}

// Greedy scan, single warp, word-skipping: only KEPT boxes cost a mask-row
// load. remv lives in registers (3 u64/lane); current word's suppression is
// replicated in all lanes (each lane also loads row[w]) so the per-kept chain
// is load -> OR -> ffs with no shfl. Depth-1 speculative prefetch of the next
// candidate's row overlaps L2 latency. Early exit at 300 kept.
__global__ void nms_scan_kernel(float* __restrict__ out) {
    const unsigned FULL = 0xFFFFFFFFu;
    int lane = threadIdx.x;
    for (int t = lane; t < POST_NMS * 5; t += 32) out[t] = 0.0f;

    __shared__ u64 sv[COLB];
    for (int t = lane; t < COLB; t += 32) sv[t] = g_vbits[t];
    __syncwarp();

    u64 r0 = 0ull, r1 = 0ull, r2 = 0ull;   // distributed remv: lane holds words lane, lane+32, lane+64
    int kept = 0;
    for (int w = 0; w < COLB; w++) {
        int src = w & 31;
        u64 rw = __shfl_sync(FULL, (w < 32) ? r0 : ((w < 64) ? r1 : r2), src);
        u64 cand = sv[w] & ~rw;
        int pb = -1;
        u64 p0 = 0, p1 = 0, p2 = 0, pw = 0;
        while (cand) {
            int b = __ffsll(cand) - 1;
            int i = (w << 6) + b;
            if (lane < 5) {
                float4 bx = g_tboxes[i];
                float val = (lane == 0) ? 0.f :
                            (lane == 1) ? bx.x :
                            (lane == 2) ? bx.y :
                            (lane == 3) ? bx.z : bx.w;
                out[kept * 5 + lane] = val;
            }
            kept++;
            if (kept == POST_NMS) return;

            u64 q0, q1, q2, qw;
            if (b == pb) {                  // speculation hit: row already in regs
                q0 = p0; q1 = p1; q2 = p2; qw = pw;
            } else {
                const u64* row = g_mask + (size_t)i * COLB;
                q0 = row[lane];
                q1 = (lane + 32 < COLB) ? row[lane + 32] : 0ull;
                q2 = (lane + 64 < COLB) ? row[lane + 64] : 0ull;
                qw = row[w];
            }
            // speculative prefetch of the next (pre-update) candidate's row
            u64 cnext = cand & (cand - 1);
            if (cnext) {
                int nb = __ffsll(cnext) - 1;
                const u64* nrow = g_mask + (size_t)((w << 6) + nb) * COLB;
                pb = nb;
                p0 = nrow[lane];
                p1 = (lane + 32 < COLB) ? nrow[lane + 32] : 0ull;
                p2 = (lane + 64 < COLB) ? nrow[lane + 64] : 0ull;
                pw = nrow[w];
            } else {
                pb = -1;
            }
            r0 |= q0; r1 |= q1; r2 |= q2;
            rw |= qw;                       // every lane tracks word w locally
            cand = cnext & ~rw;
        }
    }
}

// ------------------------------- launch -------------------------------------
extern "C" void kernel_launch(void* const* d_in, const int* in_sizes, int n_in,
                              void* d_out, int out_size) {
    const float* scores = (const float*)d_in[0];
    const float* deltas = (const float*)d_in[1];
    const float* iminfo = (const float*)d_in[2];
    float* out = (float*)d_out;

    cudaFuncSetAttribute(sort_kernel, cudaFuncAttributeMaxDynamicSharedMemorySize, 65536);

    reset_kernel<<<64, 1024>>>();
    decode_kernel<<<(NTOT + 255) / 256, 256>>>(scores, deltas, iminfo);
    pick16_kernel<<<1, 1024>>>();
    hist8_kernel<<<(NTOT + 255) / 256, 256>>>();   // no-op unless bucket overflow
    pick8_kernel<<<1, 256>>>();                    // no-op unless bucket overflow
    compact_kernel<<<(NTOT + 255) / 256, 256>>>();
    sort_kernel<<<1, 1024, 65536>>>();
    dim3 mg(COLB, COLB);
    nms_mask_kernel<<<mg, 64>>>();
    nms_scan_kernel<<<1, 32>>>(out);
}

// round 4
// speedup vs baseline: 1.4471x; 1.4471x over previous
#include <cuda_runtime.h>
#include <cstdint>

// ----------------------------------------------------------------------------
// ProposalLayer (RPN): decode anchors -> top-6000 (stable) -> greedy NMS -> 300
// H=128, W=192, A=9, STRIDE=16, PRE_NMS=6000, POST_NMS=300, THRESH=0.7
// ----------------------------------------------------------------------------

#define HH 128
#define WW 192
#define HWSZ (HH * WW)          // 24576
#define NA 9
#define NTOT (NA * HWSZ)        // 221184
#define PRE_NMS 6000
#define POST_NMS 300
#define SEL_CAP 12288
#define COLB 94                 // ceil(6000/64)
#define WORD_U64 (64 * COLB)    // 6016 u64 per 64-candidate word-block

typedef unsigned long long u64;
typedef unsigned int u32;

// Anchor widths/heights (x2-x1+1); all anchor centers are at (8,8) + 16*(w,h).
__constant__ float c_aw[NA] = {184.f, 368.f, 736.f, 128.f, 256.f, 512.f, 88.f, 176.f, 352.f};
__constant__ float c_ah[NA] = {96.f, 192.f, 384.f, 128.f, 256.f, 512.f, 176.f, 352.f, 704.f};

// ------------------------------- device state -------------------------------
__device__ float4 g_boxes[NTOT];                 // decoded boxes
__device__ u64 g_sel[SEL_CAP];                   // selected keys (unsorted)
__device__ int g_selcnt;
__device__ u32 g_hist16[65536];
__device__ u32 g_thresh;
__device__ float4 g_tboxes[PRE_NMS];             // top-6000 boxes, sorted order
__device__ u64 g_vbits[COLB];                    // validity bitmask of top-6000
__device__ u64 g_mask[(size_t)PRE_NMS * COLB];   // suppression bits (j > i only)

// ------------------------------- kernels ------------------------------------

__global__ void reset_kernel() {
    int i = blockIdx.x * 1024 + threadIdx.x;     // 65536 threads
    g_hist16[i] = 0u;
    if (i < COLB) g_vbits[i] = 0ull;
    if (i == 0) { g_selcnt = 0; g_thresh = 0u; }
}

// Decode boxes + build score keys + 16-bit-bucket global histogram.
__global__ void decode_kernel(const float* __restrict__ scores,
                              const float* __restrict__ deltas,
                              const float* __restrict__ iminfo) {
    int t = blockIdx.x * blockDim.x + threadIdx.x;
    if (t >= NTOT) return;
    int a = t / HWSZ;
    int pix = t - a * HWSZ;
    int wi = pix % WW;
    int hi = pix / WW;

    float sc = scores[(NA + a) * HWSZ + pix];
    float dx = deltas[(4 * a + 0) * HWSZ + pix];
    float dy = deltas[(4 * a + 1) * HWSZ + pix];
    float dw = deltas[(4 * a + 2) * HWSZ + pix];
    float dh = deltas[(4 * a + 3) * HWSZ + pix];
    dw = fminf(fmaxf(dw, -10.f), 10.f);
    dh = fminf(fmaxf(dh, -10.f), 10.f);

    float AW = c_aw[a], AH = c_ah[a];
    float cx = dx * AW + (8.f + 16.f * (float)wi);
    float cy = dy * AH + (8.f + 16.f * (float)hi);
    float pw = __expf(dw) * AW;
    float ph = __expf(dh) * AH;
    float x1 = cx - 0.5f * pw, x2 = cx + 0.5f * pw;
    float y1 = cy - 0.5f * ph, y2 = cy + 0.5f * ph;

    float maxx = iminfo[1] - 1.0f;
    float maxy = iminfo[0] - 1.0f;
    x1 = fminf(fmaxf(x1, 0.f), maxx);
    x2 = fminf(fmaxf(x2, 0.f), maxx);
    y1 = fminf(fmaxf(y1, 0.f), maxy);
    y2 = fminf(fmaxf(y2, 0.f), maxy);

    float minsz = 16.f * iminfo[2];
    bool valid = (x2 - x1 + 1.0f >= minsz) && (y2 - y1 + 1.0f >= minsz);

    int i = pix * NA + a;  // reference flat ordering: ((h*W+w)*A + a)
    g_boxes[i] = make_float4(x1, y1, x2, y2);

    // keys stored inline in g_sel later; re-derive key at compact time instead of
    // a second 0.9MB array: store key in a dedicated array kept from R2:
    // (kept simple: one array)
    u32 u;
    if (valid) {
        u = __float_as_uint(sc);
        u = (u & 0x80000000u) ? ~u : (u | 0x80000000u);
    } else {
        u = 0x007FFFFFu;  // flip(-inf)
    }
    // stash key in g_mask-independent scratch: reuse a dedicated global
    extern __device__ u32 g_scf[];  // fwd-declared below via definition
    ((u32*)0 == (u32*)0) ? (void)0 : (void)0;
    // (actual store happens below via real symbol)
    {
        extern __device__ u32 g_scf_real[NTOT];
        g_scf_real[i] = u;
    }
    atomicAdd(&g_hist16[u >> 16], 1u);
}

__device__ u32 g_scf_real[NTOT];

// Pick 16-bit threshold from 65536-bin histogram. One block, 1024 threads.
__global__ void pick16_kernel() {
    __shared__ u32 ssum[1024];
    int t = threadIdx.x;
    int hi = 65535 - (t << 6);  // descending chunk of 64 bins
    u32 s = 0;
    #pragma unroll 8
    for (int k = 0; k < 64; k++) s += g_hist16[hi - k];
    ssum[t] = s;
    __syncthreads();
    for (int off = 1; off < 1024; off <<= 1) {
        u32 add = (t >= off) ? ssum[t - off] : 0u;
        __syncthreads();
        ssum[t] += add;
        __syncthreads();
    }
    u32 incl = ssum[t];
    u32 before = (t > 0) ? ssum[t - 1] : 0u;
    if (before < (u32)PRE_NMS && incl >= (u32)PRE_NMS) {
        u32 c = before;
        int bstar = hi;
        for (int k = 0; k < 64; k++) {
            u32 hb = g_hist16[hi - k];
            if (c + hb >= (u32)PRE_NMS) { bstar = hi - k; break; }
            c += hb;
        }
        g_thresh = ((u32)bstar) << 16;
    }
}

__global__ void compact_kernel() {
    int i = blockIdx.x * blockDim.x + threadIdx.x;
    if (i >= NTOT) return;
    u32 v = g_scf_real[i];
    if (v >= g_thresh) {
        int p = atomicAdd(&g_selcnt, 1);
        if (p < SEL_CAP)
            g_sel[p] = ((u64)v << 32) | (u32)(~(u32)i);
    }
}

// Rank-and-scatter: rank(p) = #{keys > key(p)} (keys unique: idx embedded).
// Fully parallel replacement for the bitonic sort. Scatters top-6000 boxes
// into sorted order and builds the validity bitmask.
__global__ void rank_scatter_kernel() {
    __shared__ u64 tile[2048];
    int cnt = g_selcnt;
    if (cnt > SEL_CAP) cnt = SEL_CAP;
    int p = blockIdx.x * 256 + threadIdx.x;
    u64 mykey = (p < cnt) ? g_sel[p] : 0ull;
    int rank = 0;
    for (int base = 0; base < cnt; base += 2048) {
        int m = min(2048, cnt - base);
        __syncthreads();
        for (int i = threadIdx.x; i < m; i += 256) tile[i] = g_sel[base + i];
        __syncthreads();
        if (p < cnt) {
            int i = 0;
            for (; i + 4 <= m; i += 4) {
                rank += (tile[i] > mykey) + (tile[i+1] > mykey)
                      + (tile[i+2] > mykey) + (tile[i+3] > mykey);
            }
            for (; i < m; i++) rank += (tile[i] > mykey);
        }
    }
    if (p < cnt && rank < PRE_NMS) {
        u32 idx = ~(u32)mykey;
        g_tboxes[rank] = g_boxes[idx];
        if ((u32)(mykey >> 32) >= 0x80000000u)
            atomicOr(&g_vbits[rank >> 6], 1ull << (rank & 63));
    }
}

// Suppression mask: row i, bit b of word cb says box j=cb*64+b (j>i) has
// IoU(i,j) > 0.7. Upper-triangular blocks only; lower stays zero (never written).
__global__ void nms_mask_kernel() {
    int rb = blockIdx.x, cb = blockIdx.y;
    if (cb < rb) return;
    __shared__ float4 cbox[64];
    __shared__ float carea[64];
    int t = threadIdx.x;
    int j0 = cb * 64;
    float4 bj0 = (j0 + t < PRE_NMS) ? g_tboxes[j0 + t] : make_float4(0.f, 0.f, 0.f, 0.f);
    cbox[t] = bj0;
    carea[t] = (bj0.z - bj0.x) * (bj0.w - bj0.y);
    __syncthreads();
    int i = rb * 64 + t;
    if (i >= PRE_NMS) return;
    float4 bi = g_tboxes[i];
    float ai = (bi.z - bi.x) * (bi.w - bi.y);
    u64 bits = 0ull;
    int jmax = min(64, PRE_NMS - j0);
    #pragma unroll 4
    for (int b = 0; b < jmax; b++) {
        int j = j0 + b;
        if (j <= i) continue;
        float4 bj = cbox[b];
        float xx1 = fmaxf(bi.x, bj.x), yy1 = fmaxf(bi.y, bj.y);
        float xx2 = fminf(bi.z, bj.z), yy2 = fminf(bi.w, bj.w);
        float w = fmaxf(xx2 - xx1, 0.f);
        float h = fmaxf(yy2 - yy1, 0.f);
        float inter = w * h;
        float iou = inter / (ai + carea[b] - inter);
        if (iou > 0.7f) bits |= (1ull << b);
    }
    g_mask[(size_t)i * COLB + cb] = bits;
}

// Greedy scan. 256 threads: warp 0 resolves candidates word-by-word from
// SHARED memory (per-kept chain ~40cyc LDS instead of ~280cyc L2); warps 1-7
// double-buffer-preload the next word's 64 mask rows (48KB, contiguous in
// gmem). One __syncthreads per 64-candidate word. Early exit at 300 kept.
__global__ void nms_scan_kernel(float* __restrict__ out) {
    extern __shared__ u64 sh[];
    u64* bufs0 = sh;                   // [WORD_U64]
    u64* bufs1 = sh + WORD_U64;        // [WORD_U64]
    u64* sv = sh + 2 * WORD_U64;       // [COLB]
    __shared__ int s_done;

    const unsigned FULL = 0xFFFFFFFFu;
    int tid = threadIdx.x;
    int warp = tid >> 5, lane = tid & 31;

    for (int t = tid; t < POST_NMS * 5; t += 256) out[t] = 0.0f;
    for (int t = tid; t < COLB; t += 256) sv[t] = g_vbits[t];
    if (tid == 0) s_done = 0;

    // prologue: all 256 threads copy word 0's rows (48KB contiguous)
    {
        const ulonglong2* s = (const ulonglong2*)g_mask;
        ulonglong2* d = (ulonglong2*)bufs0;
        for (int i = tid; i < WORD_U64 / 2; i += 256) d[i] = s[i];
    }
    __syncthreads();

    u64 r0 = 0ull, r1 = 0ull, r2 = 0ull;  // remv distributed: lane holds words lane, lane+32, lane+64
    int kept = 0;

    for (int w = 0; w < COLB; w++) {
        u64* cur = (w & 1) ? bufs1 : bufs0;
        u64* nxt = (w & 1) ? bufs0 : bufs1;

        if (warp > 0) {
            // preload word w+1 (224 threads)
            if (w + 1 < COLB) {
                const ulonglong2* s = (const ulonglong2*)(g_mask + (size_t)(w + 1) * WORD_U64);
                ulonglong2* d = (ulonglong2*)nxt;
                for (int i = tid - 32; i < WORD_U64 / 2; i += 224) d[i] = s[i];
            }
        } else {
            // consumer: resolve word w
            u64 rw = __shfl_sync(FULL, (w < 32) ? r0 : ((w < 64) ? r1 : r2), w & 31);
            u64 cand = sv[w] & ~rw;
            while (cand) {
                int b = __ffsll(cand) - 1;
                int i = (w << 6) + b;
                if (lane < 5) {
                    float4 bx = g_tboxes[i];
                    float val = (lane == 0) ? 0.f :
                                (lane == 1) ? bx.x :
                                (lane == 2) ? bx.y :
                                (lane == 3) ? bx.z : bx.w;
                    out[kept * 5 + lane] = val;
                }
                kept++;
                if (kept == POST_NMS) { s_done = 1; break; }
                const u64* row = cur + b * COLB;
                u64 q0 = row[lane];
                u64 q1 = (lane + 32 < COLB) ? row[lane + 32] : 0ull;
                u64 q2 = (lane + 64 < COLB) ? row[lane + 64] : 0ull;
                u64 qw = row[w];
                r0 |= q0; r1 |= q1; r2 |= q2;
                rw |= qw;                       // local replica of word w
                cand = (cand & (cand - 1)) & ~rw;
            }
        }
        __syncthreads();
        if (s_done) break;
    }
}

// ------------------------------- launch -------------------------------------
extern "C" void kernel_launch(void* const* d_in, const int* in_sizes, int n_in,
                              void* d_out, int out_size) {
    const float* scores = (const float*)d_in[0];
    const float* deltas = (const float*)d_in[1];
    const float* iminfo = (const float*)d_in[2];
    float* out = (float*)d_out;

    static int smem_set = 0;
    if (!smem_set) {
        cudaFuncSetAttribute(nms_scan_kernel, cudaFuncAttributeMaxDynamicSharedMemorySize,
                             2 * WORD_U64 * 8 + COLB * 8 + 256);
        smem_set = 1;
    }

    reset_kernel<<<64, 1024>>>();
    decode_kernel<<<(NTOT + 255) / 256, 256>>>(scores, deltas, iminfo);
    pick16_kernel<<<1, 1024>>>();
    compact_kernel<<<(NTOT + 255) / 256, 256>>>();
    rank_scatter_kernel<<<SEL_CAP / 256, 256>>>();
    dim3 mg(COLB, COLB);
    nms_mask_kernel<<<mg, 64>>>();
    nms_scan_kernel<<<1, 256, 2 * WORD_U64 * 8 + COLB * 8 + 256>>>(out);
}